// round 7
// baseline (speedup 1.0000x reference)
#include <cuda_runtime.h>

#define BB 2
#define CC 128
#define TT 5
#define HH 48
#define WW 48
#define HWP 2304      // H*W
#define NH 64         // heads
#define TC 4          // context frames
#define NK 196        // Tc*7*7
#define FRAME (TC * HWP)
#define TQ 4          // query pixels per attn block
#define TW 10         // tile width  (7 + TQ - 1 = 10)
#define NTILE 280     // TC * 7 * TW
#define HCH 32        // head chunk

// Scratch (allocation-free rule: __device__ globals)
__device__ float g_q   [BB * HWP * NH];      // [b][pix][h]
__device__ float g_phiT[BB * NH * FRAME];    // [b][h][t][pix]
__device__ float g_gvT [BB * NH * FRAME];    // [b][h][t][pix]
__device__ float g_z   [BB * HWP * NH];      // [b][p2][h2]  (scrambled Y)

#define TP 32  // pixels per projection tile
#define NPB (HWP / TP)          // 72

// ---------------------------------------------------------------------------
// Merged projections. blocks [0, BB*TC*NPB): ctx (phi+g). Rest: query theta.
// ---------------------------------------------------------------------------
__global__ __launch_bounds__(128) void proj_kernel(
        const float* __restrict__ x,
        const float* __restrict__ w_theta,
        const float* __restrict__ w_phi,
        const float* __restrict__ w_g) {
    __shared__ float xs[CC][TP];
    int blk = blockIdx.x;

    if (blk < BB * TC * NPB) {
        // ----- context frames: phi -> g_phiT, g -> g_gvT -----
        int pb = blk % NPB;
        int t  = (blk / NPB) % TC;
        int b  = blk / (NPB * TC);
        int pix0 = pb * TP;

        const float* xb = x + ((long)(b * CC) * TT + (t + 1)) * HWP + pix0;
        for (int i = threadIdx.x; i < CC * TP; i += 128) {
            int c = i / TP, pp = i % TP;
            xs[c][pp] = xb[(long)c * TT * HWP + pp];
        }
        __syncthreads();

        int r = threadIdx.x;
        const float* wr = (r < NH) ? (w_phi + r * CC) : (w_g + (r - NH) * CC);

        float acc[TP];
#pragma unroll
        for (int pp = 0; pp < TP; pp++) acc[pp] = 0.f;
        for (int c = 0; c < CC; c++) {
            float w = wr[c];
#pragma unroll
            for (int v = 0; v < TP / 4; v++) {
                float4 xv = *(const float4*)&xs[c][v * 4];
                acc[v*4+0] += w * xv.x;  acc[v*4+1] += w * xv.y;
                acc[v*4+2] += w * xv.z;  acc[v*4+3] += w * xv.w;
            }
        }
        float* ob = ((r < NH) ? g_phiT : g_gvT)
                  + ((long)(b * NH + (r & (NH - 1))) * TC + t) * HWP + pix0;
#pragma unroll
        for (int pp = 0; pp < TP; pp += 4)
            *(float4*)(ob + pp) = make_float4(acc[pp], acc[pp+1], acc[pp+2], acc[pp+3]);
    } else {
        // ----- query frame: theta -> g_q -----
        int blk2 = blk - BB * TC * NPB;
        int pb = blk2 % NPB;
        int b  = blk2 / NPB;
        int pix0 = pb * TP;

        const float* xb = x + ((long)(b * CC) * TT) * HWP + pix0;
        for (int i = threadIdx.x; i < CC * TP; i += 128) {
            int c = i / TP, pp = i % TP;
            xs[c][pp] = xb[(long)c * TT * HWP + pp];
        }
        __syncthreads();

        int r  = threadIdx.x & 63;
        int hf = threadIdx.x >> 6;      // pixel half
        const float* wr = w_theta + r * CC;

        float acc[16];
#pragma unroll
        for (int pp = 0; pp < 16; pp++) acc[pp] = 0.f;
        for (int c = 0; c < CC; c++) {
            float w = wr[c];
#pragma unroll
            for (int v = 0; v < 4; v++) {
                float4 xv = *(const float4*)&xs[c][hf * 16 + v * 4];
                acc[v*4+0] += w * xv.x;  acc[v*4+1] += w * xv.y;
                acc[v*4+2] += w * xv.z;  acc[v*4+3] += w * xv.w;
            }
        }
        long base = (long)b * HWP + pix0 + hf * 16;
#pragma unroll
        for (int pp = 0; pp < 16; pp++) g_q[(base + pp) * NH + r] = acc[pp];
    }
}

// ---------------------------------------------------------------------------
// Attention, 4 query pixels per block (same row). Window union (7 rows x
// 10 cols x 4 frames) staged in smem per 32-head chunk; buffer reused for
// phi (QK) then g (AV). 256 threads. Writes Y in the reference's scrambled
// layout: Z[b][p2][h2] with p2=(p%36)*64+h', h2=p/36.
// ---------------------------------------------------------------------------
__global__ __launch_bounds__(256) void attn_kernel() {
    __shared__ float tile[HCH * NTILE];   // 35840 B
    __shared__ float att_s[TQ][NK];
    __shared__ float qs[TQ][NH];
    __shared__ int   kpos[NK];
    __shared__ float redm[8], reds[8];

    int bq   = blockIdx.x;
    int b    = bq / (HWP / TQ);
    int pix0 = (bq % (HWP / TQ)) * TQ;
    int y0   = pix0 / WW;
    int x0   = pix0 % WW;                 // multiple of 4; row-contained
    int tid  = threadIdx.x;

    {   // q-vectors: 256 consecutive floats, coalesced
        int q = tid >> 6, h = tid & 63;
        qs[q][h] = g_q[((long)b * HWP + pix0 + q) * NH + h];
    }
    if (tid < NK) {                       // key -> tile position (query 0)
        int tf = tid / 49, o = tid % 49, i = o / 7, j = o % 7;
        kpos[tid] = (tf * 7 + i) * TW + j;
    }
    __syncthreads();

    const float* phib = g_phiT + (long)b * NH * FRAME;
    const float* gvb  = g_gvT  + (long)b * NH * FRAME;

    // ---- QK over two head chunks ----
    int qfix = tid & 3;                   // task stride 256 keeps q fixed
    for (int c = 0; c < 2; c++) {
        int h0 = c * HCH;
        for (int idx = tid; idx < HCH * NTILE; idx += 256) {
            int hl = idx / NTILE, rem = idx % NTILE;
            int tf = rem / 70, p = rem % 70, i = p / TW, j = p % TW;
            int gy = min(max(y0 - 3 + i, 0), HH - 1);
            int gx = min(max(x0 - 3 + j, 0), WW - 1);
            tile[idx] = phib[(long)(h0 + hl) * FRAME + tf * HWP + gy * WW + gx];
        }
        __syncthreads();

        float qreg[HCH];
#pragma unroll
        for (int hl = 0; hl < HCH; hl++) qreg[hl] = qs[qfix][h0 + hl];

        for (int task = tid; task < TQ * NK; task += 256) {
            int k   = task >> 2;
            int pos = kpos[k] + qfix;
            float d = 0.f;
#pragma unroll
            for (int hl = 0; hl < HCH; hl++)
                d += qreg[hl] * tile[hl * NTILE + pos];
            if (c == 0) att_s[qfix][k] = d;
            else        att_s[qfix][k] = (att_s[qfix][k] + d) * 8.0f;  // *sqrt(64)
        }
        __syncthreads();
    }

    // ---- softmax: 64 threads (2 warps) per query ----
    int q    = tid >> 6;
    int l    = tid & 63;
    int warp = tid >> 5;
    float m = -1e30f;
    for (int k = l; k < NK; k += 64) m = fmaxf(m, att_s[q][k]);
#pragma unroll
    for (int s = 16; s > 0; s >>= 1) m = fmaxf(m, __shfl_xor_sync(0xffffffffu, m, s));
    if ((tid & 31) == 0) redm[warp] = m;
    __syncthreads();
    m = fmaxf(redm[q * 2], redm[q * 2 + 1]);

    float ss = 0.f;
    for (int k = l; k < NK; k += 64) {
        float e = __expf(att_s[q][k] - m);
        att_s[q][k] = e;
        ss += e;
    }
#pragma unroll
    for (int s = 16; s > 0; s >>= 1) ss += __shfl_xor_sync(0xffffffffu, ss, s);
    if ((tid & 31) == 0) reds[warp] = ss;
    __syncthreads();
    float inv = 1.f / (reds[q * 2] + reds[q * 2 + 1]);
    for (int k = l; k < NK; k += 64) att_s[q][k] *= inv;
    __syncthreads();

    // ---- AV (scrambled): G[k,h'] = g(head=(64k+h')/196, key=(64k+h')%196) ----
    float acc = 0.f;
    {
        int h1 = l;                       // h' = tid & 63
        for (int c = 0; c < 2; c++) {
            int h0 = c * HCH;
            for (int idx = tid; idx < HCH * NTILE; idx += 256) {
                int hl = idx / NTILE, rem = idx % NTILE;
                int tf = rem / 70, p = rem % 70, i = p / TW, j = p % TW;
                int gy = min(max(y0 - 3 + i, 0), HH - 1);
                int gx = min(max(x0 - 3 + j, 0), WW - 1);
                tile[idx] = gvb[(long)(h0 + hl) * FRAME + tf * HWP + gy * WW + gx];
            }
            __syncthreads();

            // chunk boundary in k: hh = (64k+h')/196 crosses 32 at 6272
            int kmid = (6335 - h1) >> 6;              // ceil((6272-h')/64)
            int klo  = c ? kmid : 0;
            int khi  = c ? NK   : kmid;
            int kk   = c ? (klo * 64 + h1 - 6272) : h1;
            int hl   = 0;
#pragma unroll 7
            for (int k = klo; k < khi; k++) {
                acc += att_s[q][k] * tile[hl * NTILE + kpos[kk] + q];
                kk += 64;
                if (kk >= NK) { kk -= NK; hl++; }
            }
            __syncthreads();
        }
    }

    // scrambled Y store: Y[b,p,h'] -> Z[b, (p%36)*64+h', p/36]
    {
        int p  = pix0 + q;
        int p2 = (p % 36) * 64 + l;
        int h2 = p / 36;
        g_z[((long)b * HWP + p2) * NH + h2] = acc;
    }
}

// ---------------------------------------------------------------------------
// Out projection + residual: out[b,c,p2] = x[b,c,0,p2] + sum_h2 w_out[c,h2]*Z[b,p2,h2]
// block = 128 (c = tid), 32 pixels per block; fully coalesced Z loads.
// ---------------------------------------------------------------------------
#define OPX 32
__global__ __launch_bounds__(128) void outproj_kernel(
        const float* __restrict__ x,
        const float* __restrict__ w_out,
        float* __restrict__ out) {
    int blk = blockIdx.x;
    int b   = blk / (HWP / OPX);
    int p20 = (blk % (HWP / OPX)) * OPX;
    int tid = threadIdx.x;

    __shared__ float zt[OPX * NH];        // 8 KB, [px][h2]
    for (int i = tid; i < OPX * NH; i += 128)
        zt[i] = g_z[((long)b * HWP + p20) * NH + i];
    __syncthreads();

    int c = tid;
    const float* wr = w_out + c * NH;

    float acc[OPX];
#pragma unroll
    for (int j = 0; j < OPX; j++) acc[j] = 0.f;

    for (int h2 = 0; h2 < NH; h2++) {
        float w = wr[h2];
#pragma unroll
        for (int j = 0; j < OPX; j++) acc[j] += w * zt[j * NH + h2];
    }

    const float* xr   = x   + (((long)(b * CC + c)) * TT + 0) * HWP + p20;
    float*       orow = out + ((long)(b * CC + c)) * HWP + p20;
#pragma unroll
    for (int j = 0; j < OPX; j += 4) {
        float4 xv = *(const float4*)(xr + j);
        *(float4*)(orow + j) = make_float4(xv.x + acc[j],     xv.y + acc[j + 1],
                                           xv.z + acc[j + 2], xv.w + acc[j + 3]);
    }
}

extern "C" void kernel_launch(void* const* d_in, const int* in_sizes, int n_in,
                              void* d_out, int out_size) {
    const float* x       = (const float*)d_in[0];
    const float* w_theta = (const float*)d_in[1];
    const float* w_phi   = (const float*)d_in[2];
    const float* w_g     = (const float*)d_in[3];
    const float* w_out   = (const float*)d_in[4];
    float* out = (float*)d_out;

    proj_kernel<<<BB * TC * NPB + BB * NPB, 128>>>(x, w_theta, w_phi, w_g);
    attn_kernel<<<BB * (HWP / TQ), 256>>>();
    outproj_kernel<<<BB * (HWP / OPX), 128>>>(x, w_out, out);
}